// round 2
// baseline (speedup 1.0000x reference)
#include <cuda_runtime.h>

typedef unsigned long long ull;

#define TILE_E 128
#define K1     214
#define K1P    216
#define SA     130      // A^T row stride (even -> 8B-aligned edge pairs)
#define HID    128
#define NH2    32

__device__ __forceinline__ ull dup2(float w) {
    ull r;
    asm("mov.b64 %0, {%1, %1};" : "=l"(r) : "f"(w));
    return r;
}
__device__ __forceinline__ void fma2(ull& c, ull a, ull b) {
    asm("fma.rn.f32x2 %0, %1, %2, %0;" : "+l"(c) : "l"(a), "l"(b));
}
__device__ __forceinline__ void unpack2(ull v, float& lo, float& hi) {
    asm("mov.b64 {%0, %1}, %2;" : "=f"(lo), "=f"(hi) : "l"(v));
}

extern "C" __global__ void __launch_bounds__(256, 1)
edge_mlp_kernel(const float* __restrict__ x,
                const float* __restrict__ efeat,
                const float* __restrict__ nodef,
                const float* __restrict__ edgef,
                const int*   __restrict__ src,
                const int*   __restrict__ dst,
                const float* __restrict__ W1,
                const float* __restrict__ b1,
                const float* __restrict__ W2,
                const float* __restrict__ b2,
                const float* __restrict__ W3,
                const float* __restrict__ b3,
                float* __restrict__ out,
                int E)
{
    extern __shared__ float sm[];
    float* As  = sm;               // [K1P][SA]  (reused as h1^T [HID][SA] later)
    float* Ws  = As + K1P * SA;    // [8][HID]   W1 k-chunk
    float* W2T = Ws + 8 * HID;     // [HID][33]  W2 transposed
    float* h2s = W2T + HID * 33;   // [TILE_E][33]

    const int tid   = threadIdx.x;
    const int ebase = blockIdx.x * TILE_E;

    // ---------------- gather A^T tile (coalesced: 16 lanes span one feature row) ---
    {
        const int lane   = tid & 31;
        const int l      = lane & 15;
        const int estart = (tid >> 5) * 2 + (lane >> 4);
        const float4* x4 = (const float4*)x;
        const float4* e4 = (const float4*)efeat;
        const float4  z  = make_float4(0.f, 0.f, 0.f, 0.f);
        for (int eb = estart; eb < TILE_E; eb += 16) {
            const int  eg    = ebase + eb;
            const bool valid = (eg < E);
            int s = 0, d = 0;
            if (valid) { s = src[eg]; d = dst[eg]; }
            const float4 v0 = valid ? x4[s * 16 + l] : z;
            const float4 v1 = valid ? x4[d * 16 + l] : z;
            const float4 v2 = valid ? e4[(size_t)eg * 16 + l] : z;
            const int k0 = 4 * l;
            As[(k0 + 0) * SA + eb] = v0.x;
            As[(k0 + 1) * SA + eb] = v0.y;
            As[(k0 + 2) * SA + eb] = v0.z;
            As[(k0 + 3) * SA + eb] = v0.w;
            As[(64 + k0 + 0) * SA + eb] = v1.x;
            As[(64 + k0 + 1) * SA + eb] = v1.y;
            As[(64 + k0 + 2) * SA + eb] = v1.z;
            As[(64 + k0 + 3) * SA + eb] = v1.w;
            As[(128 + k0 + 0) * SA + eb] = v2.x;
            As[(128 + k0 + 1) * SA + eb] = v2.y;
            As[(128 + k0 + 2) * SA + eb] = v2.z;
            As[(128 + k0 + 3) * SA + eb] = v2.w;
            if (l < 10) {
                As[(192 + l) * SA + eb] = valid ? nodef[s * 10 + l] : 0.f;
                As[(202 + l) * SA + eb] = valid ? nodef[d * 10 + l] : 0.f;
            }
            if (l < 2) {
                As[(212 + l) * SA + eb] = valid ? edgef[(size_t)eg * 2 + l] : 0.f;
                As[(214 + l) * SA + eb] = 0.f;   // K padding rows
            }
        }
    }

    // stage W2^T (disjoint smem region, synced by layer-1 barriers)
    for (int t = tid; t < HID * NH2; t += 256) {
        const int k = t & (HID - 1);
        const int c = t >> 7;
        W2T[k * 33 + c] = W2[c * HID + k];
    }

    const int tx = tid & 15;    // hidden group (interleaved j = tx + 16*i)
    const int ty = tid >> 4;    // edge group
    const int e0 = ty * 8;

    // ---------------- layer 1: [128e][214] @ W1^T -> h1[128e][128], f32x2 packed --
    ull acc[8][4];
    #pragma unroll
    for (int i = 0; i < 8; ++i)
        #pragma unroll
        for (int p = 0; p < 4; ++p) acc[i][p] = 0ull;

    for (int kb = 0; kb < K1P; kb += 8) {
        __syncthreads();
        for (int t = tid; t < 8 * HID; t += 256) {
            const int j  = t >> 3;
            const int kk = t & 7;
            const int k  = kb + kk;
            Ws[kk * HID + j] = (k < K1) ? W1[j * K1 + k] : 0.f;
        }
        __syncthreads();
        #pragma unroll
        for (int kk = 0; kk < 8; ++kk) {
            ull a[4];
            #pragma unroll
            for (int p = 0; p < 4; ++p)
                a[p] = *(const ull*)(As + (kb + kk) * SA + e0 + 2 * p);
            #pragma unroll
            for (int i = 0; i < 8; ++i) {
                const ull bd = dup2(Ws[kk * HID + tx + 16 * i]);
                #pragma unroll
                for (int p = 0; p < 4; ++p) fma2(acc[i][p], a[p], bd);
            }
        }
    }

    __syncthreads();   // all As reads done before overwriting with h1^T

    #pragma unroll
    for (int i = 0; i < 8; ++i) {
        const int   j  = tx + 16 * i;
        const float bj = b1[j];
        #pragma unroll
        for (int p = 0; p < 4; ++p) {
            float lo, hi;
            unpack2(acc[i][p], lo, hi);
            lo = fmaxf(lo + bj, 0.f);
            hi = fmaxf(hi + bj, 0.f);
            As[j * SA + e0 + 2 * p]     = lo;
            As[j * SA + e0 + 2 * p + 1] = hi;
        }
    }
    __syncthreads();

    // ---------------- layer 2: h1[128e][128] @ W2^T -> h2[128e][32] -----------------
    ull acc2[2][4];
    #pragma unroll
    for (int c = 0; c < 2; ++c)
        #pragma unroll
        for (int p = 0; p < 4; ++p) acc2[c][p] = 0ull;

    #pragma unroll 8
    for (int k = 0; k < HID; ++k) {
        ull a[4];
        #pragma unroll
        for (int p = 0; p < 4; ++p)
            a[p] = *(const ull*)(As + k * SA + e0 + 2 * p);
        #pragma unroll
        for (int c = 0; c < 2; ++c) {
            const ull bd = dup2(W2T[k * 33 + tx + 16 * c]);
            #pragma unroll
            for (int p = 0; p < 4; ++p) fma2(acc2[c][p], a[p], bd);
        }
    }

    #pragma unroll
    for (int c = 0; c < 2; ++c) {
        const int   cc = tx + 16 * c;
        const float bc = b2[cc];
        #pragma unroll
        for (int p = 0; p < 4; ++p) {
            float lo, hi;
            unpack2(acc2[c][p], lo, hi);
            lo = fmaxf(lo + bc, 0.f);
            hi = fmaxf(hi + bc, 0.f);
            h2s[(e0 + 2 * p) * 33 + cc]     = lo;
            h2s[(e0 + 2 * p + 1) * 33 + cc] = hi;
        }
    }
    __syncthreads();

    // ---------------- layer 3: h2[128e][32] @ W3^T -> out[128e][2] ------------------
    {
        const int e   = tid >> 1;
        const int cls = tid & 1;
        float sum = b3[cls];
        #pragma unroll
        for (int k = 0; k < NH2; ++k)
            sum = fmaf(h2s[e * 33 + k], W3[cls * NH2 + k], sum);
        const int eg = ebase + e;
        if (eg < E) out[(size_t)eg * 2 + cls] = sum;
    }
}

extern "C" void kernel_launch(void* const* d_in, const int* in_sizes, int n_in,
                              void* d_out, int out_size) {
    const float* x     = (const float*)d_in[0];
    const float* efeat = (const float*)d_in[1];
    const float* nodef = (const float*)d_in[2];
    const float* edgef = (const float*)d_in[3];
    const int*   src   = (const int*)d_in[4];
    const int*   dst   = (const int*)d_in[5];
    const float* W1    = (const float*)d_in[6];
    const float* b1    = (const float*)d_in[7];
    const float* W2    = (const float*)d_in[8];
    const float* b2    = (const float*)d_in[9];
    const float* W3    = (const float*)d_in[10];
    const float* b3    = (const float*)d_in[11];
    float* out = (float*)d_out;

    const int E = in_sizes[4];   // src element count
    const int blocks = (E + TILE_E - 1) / TILE_E;
    const size_t smem = (size_t)(K1P * SA + 8 * HID + HID * 33 + TILE_E * 33) * sizeof(float);

    cudaFuncSetAttribute(edge_mlp_kernel,
                         cudaFuncAttributeMaxDynamicSharedMemorySize, (int)smem);

    edge_mlp_kernel<<<blocks, 256, smem>>>(x, efeat, nodef, edgef, src, dst,
                                           W1, b1, W2, b2, W3, b3, out, E);
}

// round 3
// speedup vs baseline: 1.5096x; 1.5096x over previous
#include <cuda_runtime.h>

typedef unsigned long long ull;

#define TILE_E 128
#define K1     214
#define K1P    216
#define SA     130      // A^T row stride (even -> 8B-aligned edge pairs)
#define HID    128
#define NH2    32
#define NTHR   512

__device__ __forceinline__ ull dup2(float w) {
    ull r;
    asm("mov.b64 %0, {%1, %1};" : "=l"(r) : "f"(w));
    return r;
}
__device__ __forceinline__ void fma2(ull& c, ull a, ull b) {
    asm("fma.rn.f32x2 %0, %1, %2, %0;" : "+l"(c) : "l"(a), "l"(b));
}
__device__ __forceinline__ void unpack2(ull v, float& lo, float& hi) {
    asm("mov.b64 {%0, %1}, %2;" : "=f"(lo), "=f"(hi) : "l"(v));
}

extern "C" __global__ void __launch_bounds__(NTHR, 1)
edge_mlp_kernel(const float* __restrict__ x,
                const float* __restrict__ efeat,
                const float* __restrict__ nodef,
                const float* __restrict__ edgef,
                const int*   __restrict__ src,
                const int*   __restrict__ dst,
                const float* __restrict__ W1,
                const float* __restrict__ b1,
                const float* __restrict__ W2,
                const float* __restrict__ b2,
                const float* __restrict__ W3,
                const float* __restrict__ b3,
                float* __restrict__ out,
                int E)
{
    extern __shared__ float sm[];
    float* As  = sm;               // [K1P][SA]  (reused as h1^T [HID][SA] later)
    float* Ws  = As + K1P * SA;    // [2][8][HID] double-buffered W1 k-chunk
    float* W2T = Ws + 2 * 8 * HID; // [HID][33]  W2 transposed
    float* h2s = W2T + HID * 33;   // [TILE_E][33]

    const int tid   = threadIdx.x;
    const int ebase = blockIdx.x * TILE_E;

    // ---------------- gather A^T tile (coalesced: 16 lanes span one feature row) ---
    {
        const int lane   = tid & 31;
        const int l      = lane & 15;
        const int estart = (tid >> 5) * 2 + (lane >> 4);
        const float4* x4 = (const float4*)x;
        const float4* e4 = (const float4*)efeat;
        const float4  z  = make_float4(0.f, 0.f, 0.f, 0.f);
        for (int eb = estart; eb < TILE_E; eb += 32) {
            const int  eg    = ebase + eb;
            const bool valid = (eg < E);
            int s = 0, d = 0;
            if (valid) { s = src[eg]; d = dst[eg]; }
            const float4 v0 = valid ? x4[s * 16 + l] : z;
            const float4 v1 = valid ? x4[d * 16 + l] : z;
            const float4 v2 = valid ? e4[(size_t)eg * 16 + l] : z;
            const int k0 = 4 * l;
            As[(k0 + 0) * SA + eb] = v0.x;
            As[(k0 + 1) * SA + eb] = v0.y;
            As[(k0 + 2) * SA + eb] = v0.z;
            As[(k0 + 3) * SA + eb] = v0.w;
            As[(64 + k0 + 0) * SA + eb] = v1.x;
            As[(64 + k0 + 1) * SA + eb] = v1.y;
            As[(64 + k0 + 2) * SA + eb] = v1.z;
            As[(64 + k0 + 3) * SA + eb] = v1.w;
            As[(128 + k0 + 0) * SA + eb] = v2.x;
            As[(128 + k0 + 1) * SA + eb] = v2.y;
            As[(128 + k0 + 2) * SA + eb] = v2.z;
            As[(128 + k0 + 3) * SA + eb] = v2.w;
            if (l < 10) {
                As[(192 + l) * SA + eb] = valid ? nodef[s * 10 + l] : 0.f;
                As[(202 + l) * SA + eb] = valid ? nodef[d * 10 + l] : 0.f;
            }
            if (l < 2) {
                As[(212 + l) * SA + eb] = valid ? edgef[(size_t)eg * 2 + l] : 0.f;
                As[(214 + l) * SA + eb] = 0.f;   // K padding rows
            }
        }
    }

    // stage W2^T (disjoint smem region; synced by the layer-1 barriers)
    for (int t = tid; t < HID * NH2; t += NTHR) {
        const int k = t & (HID - 1);
        const int c = t >> 7;
        W2T[k * 33 + c] = W2[c * HID + k];
    }

    // stage W1 chunk 0 into buffer 0
    {
        int t = tid;
        #pragma unroll
        for (int r = 0; r < 2; ++r, t += NTHR) {
            const int j  = t >> 3;
            const int kk = t & 7;
            Ws[kk * HID + j] = W1[j * K1 + kk];
        }
    }
    __syncthreads();

    const int tx = tid & 15;    // hidden group (interleaved j = tx + 16*i)
    const int ty = tid >> 4;    // edge group (0..31)
    const int e0 = ty * 4;      // 4 edges per thread

    // ---------------- layer 1: [128e][214] @ W1^T -> h1[128e][128], f32x2 packed --
    ull acc[8][2];
    #pragma unroll
    for (int i = 0; i < 8; ++i) { acc[i][0] = 0ull; acc[i][1] = 0ull; }

    int buf = 0;
    for (int kb = 0; kb < K1P; kb += 8) {
        // prefetch next chunk into registers (overlaps with compute below)
        float r0 = 0.f, r1 = 0.f;
        const bool more = (kb + 8 < K1P);
        if (more) {
            int t = tid;
            int j = t >> 3, kk = t & 7, k = kb + 8 + kk;
            r0 = (k < K1) ? W1[j * K1 + k] : 0.f;
            t += NTHR;
            j = t >> 3; kk = t & 7; k = kb + 8 + kk;
            r1 = (k < K1) ? W1[j * K1 + k] : 0.f;
        }

        const float* Wc = Ws + (buf ? 8 * HID : 0);
        #pragma unroll
        for (int kk = 0; kk < 8; ++kk) {
            const float* arow = As + (kb + kk) * SA + e0;
            const ull a0 = *(const ull*)(arow);
            const ull a1 = *(const ull*)(arow + 2);
            #pragma unroll
            for (int i = 0; i < 8; ++i) {
                const ull bd = dup2(Wc[kk * HID + tx + 16 * i]);
                fma2(acc[i][0], a0, bd);
                fma2(acc[i][1], a1, bd);
            }
        }

        if (more) {
            float* Wn = Ws + (buf ? 0 : 8 * HID);
            int t = tid;
            Wn[(t & 7) * HID + (t >> 3)] = r0;
            t += NTHR;
            Wn[(t & 7) * HID + (t >> 3)] = r1;
        }
        buf ^= 1;
        __syncthreads();   // next chunk ready; also orders final As reads
    }

    // h1 = relu(acc + b1), written back transposed into As
    #pragma unroll
    for (int i = 0; i < 8; ++i) {
        const int   j  = tx + 16 * i;
        const float bj = b1[j];
        #pragma unroll
        for (int p = 0; p < 2; ++p) {
            float lo, hi;
            unpack2(acc[i][p], lo, hi);
            lo = fmaxf(lo + bj, 0.f);
            hi = fmaxf(hi + bj, 0.f);
            *(float2*)(As + j * SA + e0 + 2 * p) = make_float2(lo, hi);
        }
    }
    __syncthreads();

    // ---------------- layer 2: h1[128e][128] @ W2^T -> h2[128e][32] -----------------
    ull acc2[2][2];
    acc2[0][0] = acc2[0][1] = acc2[1][0] = acc2[1][1] = 0ull;

    #pragma unroll 8
    for (int k = 0; k < HID; ++k) {
        const float* arow = As + k * SA + e0;
        const ull a0 = *(const ull*)(arow);
        const ull a1 = *(const ull*)(arow + 2);
        #pragma unroll
        for (int c = 0; c < 2; ++c) {
            const ull bd = dup2(W2T[k * 33 + tx + 16 * c]);
            fma2(acc2[c][0], a0, bd);
            fma2(acc2[c][1], a1, bd);
        }
    }

    #pragma unroll
    for (int c = 0; c < 2; ++c) {
        const int   cc = tx + 16 * c;
        const float bc = b2[cc];
        #pragma unroll
        for (int p = 0; p < 2; ++p) {
            float lo, hi;
            unpack2(acc2[c][p], lo, hi);
            lo = fmaxf(lo + bc, 0.f);
            hi = fmaxf(hi + bc, 0.f);
            h2s[(e0 + 2 * p) * 33 + cc]     = lo;
            h2s[(e0 + 2 * p + 1) * 33 + cc] = hi;
        }
    }
    __syncthreads();

    // ---------------- layer 3: h2[128e][32] @ W3^T -> out[128e][2] ------------------
    if (tid < TILE_E * 2) {
        const int e   = tid >> 1;
        const int cls = tid & 1;
        float sum = b3[cls];
        #pragma unroll
        for (int k = 0; k < NH2; ++k)
            sum = fmaf(h2s[e * 33 + k], W3[cls * NH2 + k], sum);
        const int eg = ebase + e;
        if (eg < E) out[(size_t)eg * 2 + cls] = sum;
    }
}

extern "C" void kernel_launch(void* const* d_in, const int* in_sizes, int n_in,
                              void* d_out, int out_size) {
    const float* x     = (const float*)d_in[0];
    const float* efeat = (const float*)d_in[1];
    const float* nodef = (const float*)d_in[2];
    const float* edgef = (const float*)d_in[3];
    const int*   src   = (const int*)d_in[4];
    const int*   dst   = (const int*)d_in[5];
    const float* W1    = (const float*)d_in[6];
    const float* b1    = (const float*)d_in[7];
    const float* W2    = (const float*)d_in[8];
    const float* b2    = (const float*)d_in[9];
    const float* W3    = (const float*)d_in[10];
    const float* b3    = (const float*)d_in[11];
    float* out = (float*)d_out;

    const int E = in_sizes[4];   // src element count
    const int blocks = (E + TILE_E - 1) / TILE_E;
    const size_t smem = (size_t)(K1P * SA + 2 * 8 * HID + HID * 33 + TILE_E * 33) * sizeof(float);

    cudaFuncSetAttribute(edge_mlp_kernel,
                         cudaFuncAttributeMaxDynamicSharedMemorySize, (int)smem);

    edge_mlp_kernel<<<blocks, NTHR, smem>>>(x, efeat, nodef, edgef, src, dst,
                                            W1, b1, W2, b2, W3, b3, out, E);
}